// round 13
// baseline (speedup 1.0000x reference)
#include <cuda_runtime.h>
#include <cuda_bf16.h>
#include <cstdint>

// Problem constants
#define D      64
#define K      1024
#define HW     4096        // 64*64
#define NROWS  131072      // 32*64*64
#define MT     128         // rows per block
#define NT     64          // codes per tile
#define NTILES 16
#define XPITCH 132         // padded pitch for xs
#define BS_U32 2048        // B tile size in u32 (8KB)
#define CAP    32          // candidate slots per row

// Output layout (concatenated, float32): quantized_out (b,c,h,w), loss (b,h,w,c), idx (b,h,w)
#define LOFF   8388608
#define IOFF   16777216

// Scratch (no cudaMalloc allowed)
// g_eB: bf16 B fragments, mma.m16n8k16-ready (same layout as R11).
__device__ uint32_t g_eB[(K / 8) * 4 * 32 * 2];   // 32768 u32 = 128KB
__device__ float    g_e2[K];                      // ||e_k||^2 (exact fp32 chain)
__device__ int      g_e2max_bits;                 // max ||e||^2 as float bits

static __device__ __forceinline__ uint32_t bf2(float hi, float lo) {
    uint32_t r;
    asm("cvt.rn.satfinite.bf16x2.f32 %0, %1, %2;" : "=r"(r) : "f"(hi), "f"(lo));
    return r;
}
__device__ __forceinline__ void cp_async16(uint32_t saddr, const void* gaddr) {
    asm volatile("cp.async.cg.shared.global [%0], [%1], 16;" :: "r"(saddr), "l"(gaddr) : "memory");
}
__device__ __forceinline__ void cp_commit() {
    asm volatile("cp.async.commit_group;" ::: "memory");
}
__device__ __forceinline__ void mma_bf16(float& c0, float& c1, float& c2, float& c3,
                                         uint32_t a0, uint32_t a1, uint32_t a2, uint32_t a3,
                                         uint32_t b0, uint32_t b1) {
    asm("mma.sync.aligned.m16n8k16.row.col.f32.bf16.bf16.f32 "
        "{%0,%1,%2,%3},{%4,%5,%6,%7},{%8,%9},{%0,%1,%2,%3};"
        : "+f"(c0), "+f"(c1), "+f"(c2), "+f"(c3)
        : "r"(a0), "r"(a1), "r"(a2), "r"(a3), "r"(b0), "r"(b1));
}
// order-preserving float <-> uint encoding (unsigned compare == float compare)
__device__ __forceinline__ unsigned fenc(float f) {
    unsigned u = __float_as_uint(f);
    return (u & 0x80000000u) ? ~u : (u | 0x80000000u);
}
__device__ __forceinline__ float fdec(unsigned k) {
    unsigned u = (k & 0x80000000u) ? (k & 0x7FFFFFFFu) : ~k;
    return __uint_as_float(u);
}

// ---------------------------------------------------------------------------
// Prep: pack bf16 B fragments + exact e2 (sequential d chain) + e2max.
// ---------------------------------------------------------------------------
__global__ void vq_prep_kernel(const float* __restrict__ emb) {
    int tid = threadIdx.x;
    if (blockIdx.x < 64) {
        int gid  = blockIdx.x * 256 + tid;      // 0..16383
        int lane = gid & 31, kc = (gid >> 5) & 3, nb = gid >> 7;
        int n  = nb * 8 + (lane >> 2);
        int kb = kc * 16 + (lane & 3) * 2;
        const float* e = emb + n * D + kb;
        g_eB[gid * 2]     = bf2(e[1], e[0]);
        g_eB[gid * 2 + 1] = bf2(e[9], e[8]);
    } else {
        int k = (blockIdx.x - 64) * 256 + tid;  // blocks 64..67 -> k 0..1023
        float4 v[16];
        const float4* row = (const float4*)(emb + k * D);
#pragma unroll
        for (int i = 0; i < 16; ++i) v[i] = row[i];
        float s = 0.0f;
#pragma unroll
        for (int i = 0; i < 16; ++i) {          // sequential d = 0..63 (reference order)
            s = fmaf(v[i].x, v[i].x, s);
            s = fmaf(v[i].y, v[i].y, s);
            s = fmaf(v[i].z, v[i].z, s);
            s = fmaf(v[i].w, v[i].w, s);
        }
        g_e2[k] = s;
        atomicMax(&g_e2max_bits, __float_as_int(s));
    }
}

// ---------------------------------------------------------------------------
// Main: SINGLE-pass bf16 MMA with running-threshold candidate collection
// (tile 0 warm-up pass without collection, re-done as iteration 16),
// exact fp32-chain recheck, lex-min via u64 keys, R11 epilogue.
// ---------------------------------------------------------------------------
extern __shared__ float sm[];

__global__ __launch_bounds__(256, 3) void vq_main_kernel(
    const float* __restrict__ x,     // [b, c, h, w] fp32
    const float* __restrict__ emb,   // [K, D] fp32
    float* __restrict__ out)
{
    float*    xs = sm;                            // [64][XPITCH]
    uint32_t* Bs = (uint32_t*)(sm + D * XPITCH);  // [2][2048] double-buffered B tiles
    __shared__ float    e2sh[2][NT];
    __shared__ float    rs[MT];
    __shared__ unsigned runminU[MT];              // encoded running approx min
    __shared__ int      ccount[MT];
    __shared__ int      cidx[MT * CAP];
    __shared__ int      idxRow[MT];

    const int tid = threadIdx.x;
    const int p0  = blockIdx.x * MT;
    const int b   = p0 >> 12;
    const int s0  = p0 & 4095;
    const float* xbase = x + (size_t)b * 64 * HW + s0;

    const uint32_t bs_u = (uint32_t)__cvta_generic_to_shared(Bs);
    const uint32_t e2_u = (uint32_t)__cvta_generic_to_shared(e2sh);

    if (tid < MT) { ccount[tid] = 0; runminU[tid] = 0xFFFFFFFFu; }

    // ---- prefetch B tile 0 + e2 tile 0 ----
    {
#pragma unroll
        for (int i = 0; i < 2; ++i) {
            int c = tid + i * 256;
            cp_async16(bs_u + (uint32_t)c * 16, g_eB + c * 4);
        }
        if (tid < 16) cp_async16(e2_u + (uint32_t)tid * 16, g_e2 + tid * 4);
        cp_commit();
    }

    // ---- load x tile (float4) ----
#pragma unroll
    for (int i = 0; i < 8; ++i) {
        int f = tid + i * 256;
        int d = f >> 5, mf = f & 31;
        float4 v = *(const float4*)(xbase + d * HW + mf * 4);
        *(float4*)(xs + d * XPITCH + mf * 4) = v;
    }
    __syncthreads();

    // ---- per-row ||x||^2 (sequential d, reference order) ----
    if (tid < MT) {
        float s = 0.0f;
#pragma unroll
        for (int d = 0; d < D; ++d) {
            float v = xs[d * XPITCH + tid];
            s = fmaf(v, v, s);
        }
        rs[tid] = s;
    }

    // ---- A fragments (bf16 of x), hoisted for full K ----
    const int t = tid & 31, w = tid >> 5;
    const int r = w * 16 + (t >> 2);   // rows r and r+8
    const int q = (t & 3) * 2;
    uint32_t A[4][4];
#pragma unroll
    for (int kc = 0; kc < 4; ++kc) {
        int k = kc * 16 + q;
        A[kc][0] = bf2(xs[(k + 1) * XPITCH + r],     xs[k * XPITCH + r]);
        A[kc][1] = bf2(xs[(k + 1) * XPITCH + r + 8], xs[k * XPITCH + r + 8]);
        A[kc][2] = bf2(xs[(k + 9) * XPITCH + r],     xs[(k + 8) * XPITCH + r]);
        A[kc][3] = bf2(xs[(k + 9) * XPITCH + r + 8], xs[(k + 8) * XPITCH + r + 8]);
    }

    float rbest0 = 3.4e38f, rbest1 = 3.4e38f;
    float twoM0 = 0.f, twoM1 = 0.f;

    // ============ SINGLE PASS: 17 iterations (tile 0 redone warm at nt=16) ============
    for (int nt = 0; nt <= NTILES; ++nt) {
        const int buf = nt & 1;
        __syncthreads();   // all warps finished previous tile (incl. runmin pushes)

        if (nt < NTILES) {
            int nxt = (nt + 1) & 15;                 // nt=15 -> prefetch tile 0 again
            const uint32_t* src = g_eB + nxt * BS_U32;
            uint32_t dst = bs_u + (uint32_t)(buf ^ 1) * 8192;
#pragma unroll
            for (int i = 0; i < 2; ++i) {
                int c = tid + i * 256;
                cp_async16(dst + (uint32_t)c * 16, src + c * 4);
            }
            if (tid < 16)
                cp_async16(e2_u + (uint32_t)((buf ^ 1) * NT + tid * 4) * 4,
                           g_e2 + nxt * NT + tid * 4);
            cp_commit();
            asm volatile("cp.async.wait_group 1;" ::: "memory");
        } else {
            asm volatile("cp.async.wait_group 0;" ::: "memory");
        }
        __syncthreads();   // current tile visible

        if (nt == 0) {     // rs published by the first in-loop barrier
            float emax = sqrtf(__int_as_float(g_e2max_bits));
            twoM0 = 2.f * fmaxf(0.016f * sqrtf(rs[r])     * emax + 1e-4f, 5e-4f);
            twoM1 = 2.f * fmaxf(0.016f * sqrtf(rs[r + 8]) * emax + 1e-4f, 5e-4f);
        }
        const bool collect = (nt > 0);
        float thr0 = 0.f, thr1 = 0.f;
        if (collect) {     // runmin >= final min always -> threshold sound
            thr0 = fminf(fdec(runminU[r]),     rbest0) + twoM0;
            thr1 = fminf(fdec(runminU[r + 8]), rbest1) + twoM1;
        }

        const int tbase = ((nt == NTILES) ? 0 : nt) * NT;
        const uint32_t* bp  = Bs + buf * BS_U32;
        const float*    e2p = e2sh[buf];

#pragma unroll
        for (int nbl = 0; nbl < 8; ++nbl) {
            float c0 = 0.f, c1 = 0.f, c2 = 0.f, c3 = 0.f;
#pragma unroll
            for (int kc = 0; kc < 4; ++kc) {
                uint2 bb = *(const uint2*)(bp + ((nbl * 4 + kc) * 32 + t) * 2);
                mma_bf16(c0, c1, c2, c3, A[kc][0], A[kc][1], A[kc][2], A[kc][3], bb.x, bb.y);
            }
            float2 e2v = *(const float2*)(e2p + nbl * 8 + q);
            float v0 = fmaf(c0, -2.f, e2v.x), v1 = fmaf(c1, -2.f, e2v.y);
            float v2 = fmaf(c2, -2.f, e2v.x), v3 = fmaf(c3, -2.f, e2v.y);
            rbest0 = fminf(rbest0, fminf(v0, v1));
            rbest1 = fminf(rbest1, fminf(v2, v3));
            if (collect) {
                int n0 = tbase + nbl * 8 + q;
                if (v0 <= thr0) { int sl = atomicAdd(&ccount[r], 1);     if (sl < CAP) cidx[r * CAP + sl] = n0; }
                if (v1 <= thr0) { int sl = atomicAdd(&ccount[r], 1);     if (sl < CAP) cidx[r * CAP + sl] = n0 + 1; }
                if (v2 <= thr1) { int sl = atomicAdd(&ccount[r + 8], 1); if (sl < CAP) cidx[(r + 8) * CAP + sl] = n0; }
                if (v3 <= thr1) { int sl = atomicAdd(&ccount[r + 8], 1); if (sl < CAP) cidx[(r + 8) * CAP + sl] = n0 + 1; }
            }
        }
        // publish this thread's best-so-far (visible after next barrier)
        atomicMin(&runminU[r],     fenc(rbest0));
        atomicMin(&runminU[r + 8], fenc(rbest1));
    }

    // ============ EXACT phase: reference-rounded recheck, u64 lex-min ============
    __syncthreads();
    unsigned long long* dex = (unsigned long long*)Bs;   // 2048 u64 = 16KB scratch
#pragma unroll
    for (int i = 0; i < 8; ++i) {
        int slot = tid + i * 256;            // 0..2047
        int m = slot >> 4, sl = slot & 15;
        int cnt = ccount[m];
        unsigned long long best = ~0ULL;
        if (cnt <= CAP) {
#pragma unroll
            for (int j = 0; j < 2; ++j) {    // this thread covers slots sl and sl+16
                int s2 = sl + 16 * j;
                if (s2 < cnt) {
                    int n = cidx[m * CAP + s2];
                    const float* ep = emb + n * D;
                    float dot = 0.f;
#pragma unroll 8
                    for (int d = 0; d < D; ++d) dot = fmaf(xs[d * XPITCH + m], ep[d], dot);
                    float v = fmaf(dot, -2.f, rs[m] + g_e2[n]);   // reference rounding
                    unsigned long long e = ((unsigned long long)fenc(v) << 32) | (unsigned)n;
                    if (e < best) best = e;
                }
            }
        } else {
            // overflow fallback (prob ~0): distributed exact scan, 64 codes/thread
            for (int n = sl; n < K; n += 16) {
                const float* ep = emb + n * D;
                float dot = 0.f;
#pragma unroll 8
                for (int d = 0; d < D; ++d) dot = fmaf(xs[d * XPITCH + m], ep[d], dot);
                float v = fmaf(dot, -2.f, rs[m] + g_e2[n]);
                unsigned long long e = ((unsigned long long)fenc(v) << 32) | (unsigned)n;
                if (e < best) best = e;
            }
        }
        dex[slot] = best;
    }
    __syncthreads();
    if (tid < MT) {
        unsigned long long bv = ~0ULL;
#pragma unroll
        for (int tt = 0; tt < 16; ++tt) {
            unsigned long long e = dex[tid * 16 + tt];
            if (e < bv) bv = e;
        }
        int bi = (int)(unsigned)(bv & 0xFFFFFFFFu);
        idxRow[tid] = bi;
        out[IOFF + p0 + tid] = (float)bi;
    }
    __syncthreads();

    // ---- loss (b,h,w,c) ----
#pragma unroll
    for (int i = 0; i < 32; ++i) {
        int idx = tid + i * 256;
        int m = idx >> 6, c = idx & 63;
        float xv = xs[c * XPITCH + m];
        float ev = emb[idxRow[m] * D + c];
        float df = ev - xv;
        float tt = df * df;
        out[LOFF + (size_t)(p0 + m) * 64 + c] = tt + 0.25f * tt;
    }

    // ---- quantized_out (b,c,h,w) ----
#pragma unroll
    for (int i = 0; i < 32; ++i) {
        int idx = tid + i * 256;
        int c = idx >> 7, m = idx & 127;
        float xv = xs[c * XPITCH + m];
        float ev = emb[idxRow[m] * D + c];
        out[(size_t)(b * 64 + c) * HW + s0 + m] = xv + (ev - xv);
    }
}

// ---------------------------------------------------------------------------
extern "C" void kernel_launch(void* const* d_in, const int* in_sizes, int n_in,
                              void* d_out, int out_size)
{
    const float* x_in = (const float*)d_in[0];   // inputs  [32,64,64,64]
    const float* emb  = (const float*)d_in[1];   // embedding [1024,64]
    float* out = (float*)d_out;

    static bool attr_set = false;
    // dyn smem: xs 33792B + B tiles 2*8192B = 50176B; static ~19KB -> 3 CTAs/SM
    size_t smem_bytes = (size_t)(D * XPITCH * 4 + 2 * 8192);
    if (!attr_set) {
        cudaFuncSetAttribute(vq_main_kernel,
                             cudaFuncAttributeMaxDynamicSharedMemorySize,
                             (int)smem_bytes);
        attr_set = true;
    }

    vq_prep_kernel<<<68, 256>>>(emb);
    vq_main_kernel<<<NROWS / MT, 256, smem_bytes>>>(x_in, emb, out);
}

// round 14
// speedup vs baseline: 1.5518x; 1.5518x over previous
#include <cuda_runtime.h>
#include <cuda_bf16.h>
#include <cstdint>

// Problem constants
#define D      64
#define K      1024
#define HW     4096        // 64*64
#define NROWS  131072      // 32*64*64
#define MT     128         // rows per block
#define NT     64          // codes per tile
#define NTILES 16
#define XPITCH 132         // padded pitch for xs
#define BS_U32 2048        // B tile size in u32 (8KB)
#define CAP    16          // candidate slots per row

// Output layout (concatenated, float32): quantized_out (b,c,h,w), loss (b,h,w,c), idx (b,h,w)
#define LOFF   8388608
#define IOFF   16777216

// Scratch (no cudaMalloc allowed)
// g_eB: bf16 B fragments, mma.m16n8k16-ready (layout proven in R11).
__device__ uint32_t g_eB[(K / 8) * 4 * 32 * 2];   // 32768 u32 = 128KB
__device__ float    g_e2[K];                      // ||e_k||^2 (exact fp32 chain)
__device__ int      g_e2max_bits;                 // max ||e||^2 as float bits

static __device__ __forceinline__ uint32_t bf2(float hi, float lo) {
    uint32_t r;
    asm("cvt.rn.satfinite.bf16x2.f32 %0, %1, %2;" : "=r"(r) : "f"(hi), "f"(lo));
    return r;
}
__device__ __forceinline__ void cp_async16(uint32_t saddr, const void* gaddr) {
    asm volatile("cp.async.cg.shared.global [%0], [%1], 16;" :: "r"(saddr), "l"(gaddr) : "memory");
}
__device__ __forceinline__ void cp_commit() {
    asm volatile("cp.async.commit_group;" ::: "memory");
}
__device__ __forceinline__ void mma_bf16(float& c0, float& c1, float& c2, float& c3,
                                         uint32_t a0, uint32_t a1, uint32_t a2, uint32_t a3,
                                         uint32_t b0, uint32_t b1) {
    asm("mma.sync.aligned.m16n8k16.row.col.f32.bf16.bf16.f32 "
        "{%0,%1,%2,%3},{%4,%5,%6,%7},{%8,%9},{%0,%1,%2,%3};"
        : "+f"(c0), "+f"(c1), "+f"(c2), "+f"(c3)
        : "r"(a0), "r"(a1), "r"(a2), "r"(a3), "r"(b0), "r"(b1));
}
__device__ __forceinline__ unsigned fenc(float f) {
    unsigned u = __float_as_uint(f);
    return (u & 0x80000000u) ? ~u : (u | 0x80000000u);
}

// ---------------------------------------------------------------------------
// Prep: pack bf16 B fragments + exact e2 (sequential d chain) + e2max.
// ---------------------------------------------------------------------------
__global__ void vq_prep_kernel(const float* __restrict__ emb) {
    int tid = threadIdx.x;
    if (blockIdx.x < 64) {
        int gid  = blockIdx.x * 256 + tid;      // 0..16383
        int lane = gid & 31, kc = (gid >> 5) & 3, nb = gid >> 7;
        int n  = nb * 8 + (lane >> 2);
        int kb = kc * 16 + (lane & 3) * 2;
        const float* e = emb + n * D + kb;
        g_eB[gid * 2]     = bf2(e[1], e[0]);
        g_eB[gid * 2 + 1] = bf2(e[9], e[8]);
    } else {
        int k = (blockIdx.x - 64) * 256 + tid;  // blocks 64..67 -> k 0..1023
        float4 v[16];
        const float4* row = (const float4*)(emb + k * D);
#pragma unroll
        for (int i = 0; i < 16; ++i) v[i] = row[i];
        float s = 0.0f;
#pragma unroll
        for (int i = 0; i < 16; ++i) {          // sequential d = 0..63 (reference order)
            s = fmaf(v[i].x, v[i].x, s);
            s = fmaf(v[i].y, v[i].y, s);
            s = fmaf(v[i].z, v[i].z, s);
            s = fmaf(v[i].w, v[i].w, s);
        }
        g_e2[k] = s;
        atomicMax(&g_e2max_bits, __float_as_int(s));
    }
}

// ---------------------------------------------------------------------------
// Main: two-pass bf16 MMA filter (R11 structure) with warp remap
// (2 row-blocks x 4 n-blocks per warp -> each B fragment feeds 2 MMAs,
// halving B LDS traffic), exact fp32-chain recheck, R11 epilogue.
// ---------------------------------------------------------------------------
extern __shared__ float sm[];

__global__ __launch_bounds__(256, 3) void vq_main_kernel(
    const float* __restrict__ x,     // [b, c, h, w] fp32
    const float* __restrict__ emb,   // [K, D] fp32
    float* __restrict__ out)
{
    float*    xs = sm;                            // [64][XPITCH]
    uint32_t* Bs = (uint32_t*)(sm + D * XPITCH);  // [2][2048] double-buffered B tiles
    __shared__ float e2sh[2][NT];
    __shared__ float rs[MT];
    __shared__ float thrS[MT];
    __shared__ int   ccount[MT];
    __shared__ int   cidx[MT * CAP];
    __shared__ int   idxRow[MT];

    const int tid = threadIdx.x;
    const int p0  = blockIdx.x * MT;
    const int b   = p0 >> 12;
    const int s0  = p0 & 4095;
    const float* xbase = x + (size_t)b * 64 * HW + s0;

    const uint32_t bs_u = (uint32_t)__cvta_generic_to_shared(Bs);
    const uint32_t e2_u = (uint32_t)__cvta_generic_to_shared(e2sh);

    if (tid < MT) ccount[tid] = 0;

    // ---- prefetch B tile 0 + e2 tile 0 ----
    {
#pragma unroll
        for (int i = 0; i < 2; ++i) {
            int c = tid + i * 256;
            cp_async16(bs_u + (uint32_t)c * 16, g_eB + c * 4);
        }
        if (tid < 16) cp_async16(e2_u + (uint32_t)tid * 16, g_e2 + tid * 4);
        cp_commit();
    }

    // ---- load x tile (float4) ----
#pragma unroll
    for (int i = 0; i < 8; ++i) {
        int f = tid + i * 256;
        int d = f >> 5, mf = f & 31;
        float4 v = *(const float4*)(xbase + d * HW + mf * 4);
        *(float4*)(xs + d * XPITCH + mf * 4) = v;
    }
    __syncthreads();

    // ---- per-row ||x||^2 (sequential d, reference order) ----
    if (tid < MT) {
        float s = 0.0f;
#pragma unroll
        for (int d = 0; d < D; ++d) {
            float v = xs[d * XPITCH + tid];
            s = fmaf(v, v, s);
        }
        rs[tid] = s;
    }

    // ---- warp remap: 2 row-blocks x 4 n-blocks per warp ----
    const int t  = tid & 31, w = tid >> 5;
    const int wr = w & 3;          // row-pair index: rows wr*32 .. wr*32+31
    const int wn = w >> 2;         // n-half: nblocks wn*4 .. wn*4+3
    const int R0 = wr * 32;
    const int r0 = R0 + (t >> 2);  // thread rows: r0, r0+8, r0+16, r0+24
    const int q  = (t & 3) * 2;

    // A fragments for both row-blocks, all kc (bf16 of x), hoisted for full K
    uint32_t A[2][4][4];
#pragma unroll
    for (int blk = 0; blk < 2; ++blk) {
        int r = r0 + blk * 16;
#pragma unroll
        for (int kc = 0; kc < 4; ++kc) {
            int k = kc * 16 + q;
            A[blk][kc][0] = bf2(xs[(k + 1) * XPITCH + r],     xs[k * XPITCH + r]);
            A[blk][kc][1] = bf2(xs[(k + 1) * XPITCH + r + 8], xs[k * XPITCH + r + 8]);
            A[blk][kc][2] = bf2(xs[(k + 9) * XPITCH + r],     xs[(k + 8) * XPITCH + r]);
            A[blk][kc][3] = bf2(xs[(k + 9) * XPITCH + r + 8], xs[(k + 8) * XPITCH + r + 8]);
        }
    }

    float rbest[4] = { 3.4e38f, 3.4e38f, 3.4e38f, 3.4e38f };

    // ================= PASS 1: approx min per row =================
    for (int nt = 0; nt < NTILES; ++nt) {
        const int buf = nt & 1;
        __syncthreads();
        if (nt < NTILES - 1) {
            const uint32_t* src = g_eB + (nt + 1) * BS_U32;
            uint32_t dst = bs_u + (uint32_t)(buf ^ 1) * 8192;
#pragma unroll
            for (int i = 0; i < 2; ++i) {
                int c = tid + i * 256;
                cp_async16(dst + (uint32_t)c * 16, src + c * 4);
            }
            if (tid < 16)
                cp_async16(e2_u + (uint32_t)((buf ^ 1) * NT + tid * 4) * 4,
                           g_e2 + (nt + 1) * NT + tid * 4);
            cp_commit();
            asm volatile("cp.async.wait_group 1;" ::: "memory");
        } else {
            asm volatile("cp.async.wait_group 0;" ::: "memory");
        }
        __syncthreads();

        const uint32_t* bp  = Bs + buf * BS_U32;
        const float*    e2p = e2sh[buf];
#pragma unroll
        for (int nb = 0; nb < 4; ++nb) {
            int nblk = wn * 4 + nb;
            float c00 = 0.f, c01 = 0.f, c02 = 0.f, c03 = 0.f;
            float c10 = 0.f, c11 = 0.f, c12 = 0.f, c13 = 0.f;
#pragma unroll
            for (int kc = 0; kc < 4; ++kc) {
                uint2 bb = *(const uint2*)(bp + ((nblk * 4 + kc) * 32 + t) * 2);
                mma_bf16(c00, c01, c02, c03, A[0][kc][0], A[0][kc][1], A[0][kc][2], A[0][kc][3], bb.x, bb.y);
                mma_bf16(c10, c11, c12, c13, A[1][kc][0], A[1][kc][1], A[1][kc][2], A[1][kc][3], bb.x, bb.y);
            }
            float2 e2v = *(const float2*)(e2p + nblk * 8 + q);
            rbest[0] = fminf(rbest[0], fminf(fmaf(c00, -2.f, e2v.x), fmaf(c01, -2.f, e2v.y)));
            rbest[1] = fminf(rbest[1], fminf(fmaf(c02, -2.f, e2v.x), fmaf(c03, -2.f, e2v.y)));
            rbest[2] = fminf(rbest[2], fminf(fmaf(c10, -2.f, e2v.x), fmaf(c11, -2.f, e2v.y)));
            rbest[3] = fminf(rbest[3], fminf(fmaf(c12, -2.f, e2v.x), fmaf(c13, -2.f, e2v.y)));
        }
    }

    // reduce row-min across 4 lanes sharing each row; n-halves merge via thrS atomic-free:
    // lanes of BOTH n-half warps cover the same rows -> combine through shared mem min.
#pragma unroll
    for (int i = 0; i < 4; ++i) {
        rbest[i] = fminf(rbest[i], __shfl_xor_sync(0xffffffff, rbest[i], 1));
        rbest[i] = fminf(rbest[i], __shfl_xor_sync(0xffffffff, rbest[i], 2));
    }
    if (tid < MT) thrS[tid] = 3.4e38f;
    __syncthreads();
    if ((t & 3) == 0) {   // one lane per row per warp; 2 warps (n-halves) write each row
#pragma unroll
        for (int i = 0; i < 4; ++i)
            atomicMin((int*)&thrS[r0 + i * 8], __float_as_int(rbest[i]));   // vals > 0? no...
    }
    __syncthreads();
    // NOTE: distances can be negative; atomicMin on int works for floats of mixed sign
    // only via fenc. Redo safely: use fenc encoding in a second pass.
    if (tid < MT) thrS[tid] = 3.4e38f;
    __syncthreads();
    {
        __shared__ unsigned rminU[MT];
        if (tid < MT) rminU[tid] = 0xFFFFFFFFu;
        __syncthreads();
        if ((t & 3) == 0) {
#pragma unroll
            for (int i = 0; i < 4; ++i)
                atomicMin(&rminU[r0 + i * 8], fenc(rbest[i]));
        }
        __syncthreads();
        if (tid < MT) {
            unsigned u = rminU[tid];
            float mn = (u & 0x80000000u) ? __uint_as_float(u & 0x7FFFFFFFu) : __uint_as_float(~u);
            float emax = sqrtf(__int_as_float(g_e2max_bits));
            float m = fmaxf(0.016f * sqrtf(rs[tid]) * emax + 1e-4f, 5e-4f);
            thrS[tid] = mn + 2.f * m;
        }
    }

    // prefetch tile 0 for pass 2
    {
#pragma unroll
        for (int i = 0; i < 2; ++i) {
            int c = tid + i * 256;
            cp_async16(bs_u + (uint32_t)c * 16, g_eB + c * 4);
        }
        if (tid < 16) cp_async16(e2_u + (uint32_t)tid * 16, g_e2 + tid * 4);
        cp_commit();
    }
    __syncthreads();
    float thr[4];
#pragma unroll
    for (int i = 0; i < 4; ++i) thr[i] = thrS[r0 + i * 8];

    // ================= PASS 2: collect candidates <= thr =================
    for (int nt = 0; nt < NTILES; ++nt) {
        const int buf = nt & 1;
        __syncthreads();
        if (nt < NTILES - 1) {
            const uint32_t* src = g_eB + (nt + 1) * BS_U32;
            uint32_t dst = bs_u + (uint32_t)(buf ^ 1) * 8192;
#pragma unroll
            for (int i = 0; i < 2; ++i) {
                int c = tid + i * 256;
                cp_async16(dst + (uint32_t)c * 16, src + c * 4);
            }
            if (tid < 16)
                cp_async16(e2_u + (uint32_t)((buf ^ 1) * NT + tid * 4) * 4,
                           g_e2 + (nt + 1) * NT + tid * 4);
            cp_commit();
            asm volatile("cp.async.wait_group 1;" ::: "memory");
        } else {
            asm volatile("cp.async.wait_group 0;" ::: "memory");
        }
        __syncthreads();

        const uint32_t* bp  = Bs + buf * BS_U32;
        const float*    e2p = e2sh[buf];
#pragma unroll
        for (int nb = 0; nb < 4; ++nb) {
            int nblk = wn * 4 + nb;
            float c00 = 0.f, c01 = 0.f, c02 = 0.f, c03 = 0.f;
            float c10 = 0.f, c11 = 0.f, c12 = 0.f, c13 = 0.f;
#pragma unroll
            for (int kc = 0; kc < 4; ++kc) {
                uint2 bb = *(const uint2*)(bp + ((nblk * 4 + kc) * 32 + t) * 2);
                mma_bf16(c00, c01, c02, c03, A[0][kc][0], A[0][kc][1], A[0][kc][2], A[0][kc][3], bb.x, bb.y);
                mma_bf16(c10, c11, c12, c13, A[1][kc][0], A[1][kc][1], A[1][kc][2], A[1][kc][3], bb.x, bb.y);
            }
            float2 e2v = *(const float2*)(e2p + nblk * 8 + q);
            float v[4][2] = {
                { fmaf(c00, -2.f, e2v.x), fmaf(c01, -2.f, e2v.y) },
                { fmaf(c02, -2.f, e2v.x), fmaf(c03, -2.f, e2v.y) },
                { fmaf(c10, -2.f, e2v.x), fmaf(c11, -2.f, e2v.y) },
                { fmaf(c12, -2.f, e2v.x), fmaf(c13, -2.f, e2v.y) },
            };
            int n0 = nt * NT + nblk * 8 + q;
#pragma unroll
            for (int i = 0; i < 4; ++i) {
                int row = r0 + i * 8;
                if (v[i][0] <= thr[i]) { int sl = atomicAdd(&ccount[row], 1); if (sl < CAP) cidx[row * CAP + sl] = n0; }
                if (v[i][1] <= thr[i]) { int sl = atomicAdd(&ccount[row], 1); if (sl < CAP) cidx[row * CAP + sl] = n0 + 1; }
            }
        }
    }

    // ============ EXACT phase: reference-rounded recheck, u64 lex-min ============
    __syncthreads();
    unsigned long long* dex = (unsigned long long*)Bs;   // 2048 u64 = 16KB scratch
#pragma unroll
    for (int i = 0; i < 8; ++i) {
        int slot = tid + i * 256;            // 0..2047
        int m = slot >> 4, sl = slot & 15;
        int cnt = ccount[m];
        unsigned long long best = ~0ULL;
        if (cnt <= CAP) {
            if (sl < cnt) {
                int n = cidx[m * CAP + sl];
                const float* ep = emb + n * D;
                float dot = 0.f;
#pragma unroll 8
                for (int d = 0; d < D; ++d) dot = fmaf(xs[d * XPITCH + m], ep[d], dot);
                float vv = fmaf(dot, -2.f, rs[m] + g_e2[n]);   // reference rounding
                best = ((unsigned long long)fenc(vv) << 32) | (unsigned)n;
            }
        } else {
            // overflow fallback (prob ~0): distributed exact scan, 64 codes/thread
            for (int n = sl; n < K; n += 16) {
                const float* ep = emb + n * D;
                float dot = 0.f;
#pragma unroll 8
                for (int d = 0; d < D; ++d) dot = fmaf(xs[d * XPITCH + m], ep[d], dot);
                float vv = fmaf(dot, -2.f, rs[m] + g_e2[n]);
                unsigned long long e = ((unsigned long long)fenc(vv) << 32) | (unsigned)n;
                if (e < best) best = e;
            }
        }
        dex[slot] = best;
    }
    __syncthreads();
    if (tid < MT) {
        unsigned long long bv = ~0ULL;
#pragma unroll
        for (int tt = 0; tt < 16; ++tt) {
            unsigned long long e = dex[tid * 16 + tt];
            if (e < bv) bv = e;
        }
        int bi = (int)(unsigned)(bv & 0xFFFFFFFFu);
        idxRow[tid] = bi;
        out[IOFF + p0 + tid] = (float)bi;
    }
    __syncthreads();

    // ---- loss (b,h,w,c) ----
#pragma unroll
    for (int i = 0; i < 32; ++i) {
        int idx = tid + i * 256;
        int m = idx >> 6, c = idx & 63;
        float xv = xs[c * XPITCH + m];
        float ev = emb[idxRow[m] * D + c];
        float df = ev - xv;
        float tt = df * df;
        out[LOFF + (size_t)(p0 + m) * 64 + c] = tt + 0.25f * tt;
    }

    // ---- quantized_out (b,c,h,w) ----
#pragma unroll
    for (int i = 0; i < 32; ++i) {
        int idx = tid + i * 256;
        int c = idx >> 7, m = idx & 127;
        float xv = xs[c * XPITCH + m];
        float ev = emb[idxRow[m] * D + c];
        out[(size_t)(b * 64 + c) * HW + s0 + m] = xv + (ev - xv);
    }
}

// ---------------------------------------------------------------------------
extern "C" void kernel_launch(void* const* d_in, const int* in_sizes, int n_in,
                              void* d_out, int out_size)
{
    const float* x_in = (const float*)d_in[0];   // inputs  [32,64,64,64]
    const float* emb  = (const float*)d_in[1];   // embedding [1024,64]
    float* out = (float*)d_out;

    static bool attr_set = false;
    size_t smem_bytes = (size_t)(D * XPITCH * 4 + 2 * 8192);
    if (!attr_set) {
        cudaFuncSetAttribute(vq_main_kernel,
                             cudaFuncAttributeMaxDynamicSharedMemorySize,
                             (int)smem_bytes);
        attr_set = true;
    }

    vq_prep_kernel<<<68, 256>>>(emb);
    vq_main_kernel<<<NROWS / MT, 256, smem_bytes>>>(x_in, emb, out);
}